// round 8
// baseline (speedup 1.0000x reference)
#include <cuda_runtime.h>
#include <cuda_fp16.h>
#include <cstdint>
#include <cstddef>

#define BDIM   512
#define CELL   768
#define RANK   64
#define DF     256
#define KDNA   4000
#define NW     98304
#define HALF   49152
#define KSPLIT1 10

// GEMM2 tiling: CTA = 128m x 64n, K-chunk 32, 8 stages, double-buffered
#define KCH    32
#define NSTG   8
#define LDA    40                        // A smem stride (fp16): 80B rows, conflict-free ldmatrix
#define LDBK   40                        // B smem stride (fp16)
#define A_TILE (128 * LDA * 2)           // 10240 bytes (one of hi/lo)
#define B_TILE (64 * LDBK * 2)           // 5120 bytes
#define OFF_A(buf) ((buf) * 2 * A_TILE)  // hi at +0, lo at +A_TILE
#define OFF_B(buf) (4 * A_TILE + (buf) * B_TILE)   // 40960 + buf*5120
#define GEMM2_SMEM (4 * A_TILE + 2 * B_TILE)       // 51200

// ---------------------------------------------------------------------------
// asm helpers (all family-safe, proven in R5/R6)
// ---------------------------------------------------------------------------
__device__ __forceinline__ void mma_f16(float c[4],
                                        uint32_t a0, uint32_t a1, uint32_t a2, uint32_t a3,
                                        uint32_t b0, uint32_t b1)
{
    asm volatile(
        "mma.sync.aligned.m16n8k16.row.col.f32.f16.f16.f32 "
        "{%0,%1,%2,%3}, {%4,%5,%6,%7}, {%8,%9}, {%0,%1,%2,%3};"
        : "+f"(c[0]), "+f"(c[1]), "+f"(c[2]), "+f"(c[3])
        : "r"(a0), "r"(a1), "r"(a2), "r"(a3), "r"(b0), "r"(b1));
}
__device__ __forceinline__ uint32_t smem_u32(const void* p) {
    uint32_t a;
    asm("{ .reg .u64 t; cvta.to.shared.u64 t, %1; cvt.u32.u64 %0, t; }" : "=r"(a) : "l"(p));
    return a;
}
#define LDMX4(r0, r1, r2, r3, addr) \
    asm volatile("ldmatrix.sync.aligned.m8n8.x4.shared.b16 {%0,%1,%2,%3}, [%4];" \
                 : "=r"(r0), "=r"(r1), "=r"(r2), "=r"(r3) : "r"(addr))
#define LDMX2(r0, r1, addr) \
    asm volatile("ldmatrix.sync.aligned.m8n8.x2.shared.b16 {%0,%1}, [%2];" \
                 : "=r"(r0), "=r"(r1) : "r"(addr))
#define CP_ASYNC16(dst, src) \
    asm volatile("cp.async.cg.shared.global [%0], [%1], 16;" :: "r"(dst), "l"(src))
#define CP_COMMIT() asm volatile("cp.async.commit_group;" ::: "memory")
#define CP_WAIT1()  asm volatile("cp.async.wait_group 1;" ::: "memory")
#define CP_WAIT0()  asm volatile("cp.async.wait_group 0;" ::: "memory")

// ---------------------------------------------------------------------------
// device scratch
// ---------------------------------------------------------------------------
__device__ float g_part[KSPLIT1 * BDIM * DF];
__device__ __align__(256) __half g_Ah[BDIM * DF];
__device__ __align__(256) __half g_Al[BDIM * DF];
__device__ __align__(256) __half g_Bh[(size_t)NW * DF];   // W_hyper^T fp16 [n][k]
__device__ float g_v[(size_t)BDIM * HALF];
__device__ float g_t[BDIM * RANK];

// ---------------------------------------------------------------------------
// GEMM1: SIMT 128x128x8 SGEMM, split-K partials (proven)
// ---------------------------------------------------------------------------
__global__ void __launch_bounds__(256, 2)
sgemm_k(const float* __restrict__ A, const float* __restrict__ Bmat,
        float* __restrict__ C, int M, int N, int K)
{
    const int bn = blockIdx.x, bm = blockIdx.y, slice = blockIdx.z;
    const int kPer = K / gridDim.z;
    const int k0base = slice * kPer;

    __shared__ float As[8][128];
    __shared__ float Bs[8][128];

    const int tid = threadIdx.x;
    const int aRow = tid >> 1, aK4 = (tid & 1) * 4;
    const int bK = tid >> 5, bN4 = (tid & 31) * 4;
    const int tx = tid & 15, ty = tid >> 4;

    float acc[8][8];
    #pragma unroll
    for (int i = 0; i < 8; i++)
        #pragma unroll
        for (int j = 0; j < 8; j++) acc[i][j] = 0.f;

    const float* Aptr = A + (size_t)(bm * 128 + aRow) * K + k0base + aK4;
    const float* Bptr = Bmat + (size_t)(k0base + bK) * N + (size_t)bn * 128 + bN4;

    const int nsteps = kPer / 8;
    for (int kt = 0; kt < nsteps; kt++) {
        float4 av = *(const float4*)(Aptr);
        float4 bv = *(const float4*)(Bptr);
        As[aK4 + 0][aRow] = av.x; As[aK4 + 1][aRow] = av.y;
        As[aK4 + 2][aRow] = av.z; As[aK4 + 3][aRow] = av.w;
        *(float4*)&Bs[bK][bN4] = bv;
        __syncthreads();
        #pragma unroll
        for (int k = 0; k < 8; k++) {
            float af[8], bf[8];
            #pragma unroll
            for (int i = 0; i < 8; i++) af[i] = As[k][ty * 8 + i];
            #pragma unroll
            for (int j = 0; j < 8; j++) bf[j] = Bs[k][tx * 8 + j];
            #pragma unroll
            for (int i = 0; i < 8; i++)
                #pragma unroll
                for (int j = 0; j < 8; j++) acc[i][j] += af[i] * bf[j];
        }
        __syncthreads();
        Aptr += 8;
        Bptr += (size_t)8 * N;
    }
    float* Cbase = C + (size_t)slice * M * N;
    #pragma unroll
    for (int i = 0; i < 8; i++) {
        const int row = bm * 128 + ty * 8 + i;
        #pragma unroll
        for (int j = 0; j < 8; j += 4) {
            const int col = bn * 128 + tx * 8 + j;
            float4 v = make_float4(acc[i][j], acc[i][j+1], acc[i][j+2], acc[i][j+3]);
            *(float4*)(Cbase + (size_t)row * N + col) = v;
        }
    }
}

// ---------------------------------------------------------------------------
// reduce split-K + bias + relu -> fp16 hi/lo split of A
// ---------------------------------------------------------------------------
__global__ void reduce_relu_convert_k(const float* __restrict__ part,
                                      const float* __restrict__ bias,
                                      __half* __restrict__ Ah,
                                      __half* __restrict__ Al)
{
    const int i = blockIdx.x * 256 + threadIdx.x;
    float s = bias[i & (DF - 1)];
    #pragma unroll
    for (int sl = 0; sl < KSPLIT1; sl++) s += part[sl * (BDIM * DF) + i];
    s = fmaxf(s, 0.f);
    __half h = __float2half_rn(s);
    Ah[i] = h;
    Al[i] = __float2half_rn(s - __half2float(h));
}

// ---------------------------------------------------------------------------
// W_hyper [256, 98304] fp32 -> transposed fp16 [98304, 256] (R5-proven pattern)
// ---------------------------------------------------------------------------
__global__ void __launch_bounds__(256)
transpose_convert_k(const float* __restrict__ W, __half* __restrict__ Bh)
{
    __shared__ float s[64][65];
    const int n0 = blockIdx.x * 64, k0 = blockIdx.y * 64;
    const int t = threadIdx.x;
    {
        const int nn = t & 63, kk = t >> 6;
        #pragma unroll
        for (int p = 0; p < 16; p++) {
            int k = kk + p * 4;
            s[k][nn] = W[(size_t)(k0 + k) * NW + n0 + nn];
        }
    }
    __syncthreads();
    const int n = t >> 2, su = (t & 3) * 16;
    __align__(16) __half hi[16];
    #pragma unroll
    for (int i = 0; i < 16; i++)
        hi[i] = __float2half_rn(s[su + i][n]);
    const size_t o = (size_t)(n0 + n) * DF + k0 + su;
    *(int4*)(Bh + o)     = *(int4*)hi;
    *(int4*)(Bh + o + 8) = *(int4*)(hi + 8);
}

// ---------------------------------------------------------------------------
// fp16 2-term mma GEMM: C[128m x 64n] = A[128,256] @ B[64rows,256]^T
//   D = Ah*Bh + Al*Bh   (A exact to 22 bits, B single fp16)
// A hi/lo + B tiles via cp.async double buffer; non-trans ldmatrix (R5 mapping).
// V mode (pred==nullptr): C+bias -> vout.  U mode: contract with t -> pred.
// ---------------------------------------------------------------------------
__global__ void __launch_bounds__(256, 2)
gemm_mma_k(const __half* __restrict__ Ahg, const __half* __restrict__ Alg,
           const __half* __restrict__ Bhg, const float* __restrict__ bias,
           const float* __restrict__ tvec, float* __restrict__ vout,
           float* __restrict__ pred, int ntile0)
{
    extern __shared__ char smem[];
    const uint32_t sb = smem_u32(smem);
    const int tid = threadIdx.x, wid = tid >> 5, lane = tid & 31;
    const int bm = blockIdx.x;                 // fast dim -> B tile L2 reuse
    const int ntile = ntile0 + blockIdx.y;
    const int m0 = bm * 128, nrow0 = ntile * 64;
    const int warp_m = wid & 1, warp_n = wid >> 1;   // 2 x 4 warps: 64m x 16n
    const int g = lane >> 2, t4 = lane & 3;

    float acc[4][2][4];
    #pragma unroll
    for (int mf = 0; mf < 4; mf++)
        #pragma unroll
        for (int nf = 0; nf < 2; nf++)
            #pragma unroll
            for (int c = 0; c < 4; c++) acc[mf][nf][c] = 0.f;

    const int a_row = warp_m * 64 + (lane & 15);
    const int a_koff = (lane >> 4) * 8;
    const int b_row = lane & 7;                     // n within 8-block
    const int b_koff = ((lane >> 3) & 1) * 8;       // x2: lanes 8-15 -> k+8

    const __half* Asrc_h = Ahg + (size_t)m0 * DF;
    const __half* Asrc_l = Alg + (size_t)m0 * DF;
    const __half* Bsrc   = Bhg + (size_t)nrow0 * DF;

    auto load_stage = [&](int buf, int k0) {
        // A: 128 rows x 32 k fp16 = 4 int4/row; 512 transfers x2 (hi/lo)
        #pragma unroll
        for (int p = 0; p < 2; p++) {
            const int c = tid + p * 256;
            const int row = c >> 2, j = c & 3;
            const uint32_t so = (uint32_t)(row * LDA + j * 8) * 2;
            CP_ASYNC16(sb + OFF_A(buf) + so, Asrc_h + (size_t)row * DF + k0 + j * 8);
            CP_ASYNC16(sb + OFF_A(buf) + A_TILE + so, Asrc_l + (size_t)row * DF + k0 + j * 8);
        }
        // B: 64 rows x 32 k fp16 = 4 int4/row; 256 transfers
        {
            const int row = tid >> 2, j = tid & 3;
            CP_ASYNC16(sb + OFF_B(buf) + (uint32_t)(row * LDBK + j * 8) * 2,
                       Bsrc + (size_t)row * DF + k0 + j * 8);
        }
    };

    auto compute = [&](int buf) {
        const uint32_t ah_base = sb + OFF_A(buf);
        const uint32_t al_base = ah_base + A_TILE;
        const uint32_t b_base  = sb + OFF_B(buf);
        #pragma unroll
        for (int ks = 0; ks < 2; ks++) {
            uint32_t bh[2][2];
            #pragma unroll
            for (int nf = 0; nf < 2; nf++) {
                const uint32_t bo = (uint32_t)((warp_n * 16 + nf * 8 + b_row) * LDBK
                                               + ks * 16 + b_koff) * 2;
                LDMX2(bh[nf][0], bh[nf][1], b_base + bo);
            }
            #pragma unroll
            for (int mf = 0; mf < 4; mf++) {
                uint32_t ah[4], al[4];
                const uint32_t so = (uint32_t)((a_row + mf * 16) * LDA + ks * 16 + a_koff) * 2;
                LDMX4(ah[0], ah[1], ah[2], ah[3], ah_base + so);
                LDMX4(al[0], al[1], al[2], al[3], al_base + so);
                #pragma unroll
                for (int nf = 0; nf < 2; nf++) {
                    mma_f16(acc[mf][nf], ah[0], ah[1], ah[2], ah[3], bh[nf][0], bh[nf][1]);
                    mma_f16(acc[mf][nf], al[0], al[1], al[2], al[3], bh[nf][0], bh[nf][1]);
                }
            }
        }
    };

    load_stage(0, 0);
    CP_COMMIT();
    for (int s = 0; s < NSTG; s++) {
        if (s + 1 < NSTG) {
            load_stage((s + 1) & 1, (s + 1) * KCH);
            CP_COMMIT();
            CP_WAIT1();
        } else {
            CP_WAIT0();
        }
        __syncthreads();          // stage s data ready
        compute(s & 1);
        __syncthreads();          // free buf before next overwrite
    }

    // ------------------------- epilogue -------------------------
    if (pred == nullptr) {
        // V mode: C + bias -> vout
        #pragma unroll
        for (int mf = 0; mf < 4; mf++) {
            const int row = warp_m * 64 + mf * 16 + g;
            #pragma unroll
            for (int nf = 0; nf < 2; nf++) {
                const int col = warp_n * 16 + nf * 8 + 2 * t4;
                const float b0 = bias[nrow0 + col], b1 = bias[nrow0 + col + 1];
                const size_t base = (size_t)(m0 + row) * HALF + (nrow0 - HALF) + col;
                float2 v0 = make_float2(acc[mf][nf][0] + b0, acc[mf][nf][1] + b1);
                float2 v1 = make_float2(acc[mf][nf][2] + b0, acc[mf][nf][3] + b1);
                *(float2*)&vout[base] = v0;
                *(float2*)&vout[base + (size_t)8 * HALF] = v1;
            }
        }
    } else {
        // U mode: pred[b, ntile] = sum_col (C+bias) * t[b, col]
        float* spart = (float*)smem;             // [128][4] - overlaps buf0 (safe, last buf=1)
        #pragma unroll
        for (int mf = 0; mf < 4; mf++) {
            const int row_lo = warp_m * 64 + mf * 16 + g;
            float p0 = 0.f, p1 = 0.f;
            const float* t0p = tvec + (size_t)(m0 + row_lo) * RANK;
            const float* t1p = tvec + (size_t)(m0 + row_lo + 8) * RANK;
            #pragma unroll
            for (int nf = 0; nf < 2; nf++) {
                const int col = warp_n * 16 + nf * 8 + 2 * t4;
                const float b0 = bias[nrow0 + col], b1 = bias[nrow0 + col + 1];
                p0 += (acc[mf][nf][0] + b0) * t0p[col] + (acc[mf][nf][1] + b1) * t0p[col + 1];
                p1 += (acc[mf][nf][2] + b0) * t1p[col] + (acc[mf][nf][3] + b1) * t1p[col + 1];
            }
            p0 += __shfl_xor_sync(0xFFFFFFFF, p0, 1);
            p0 += __shfl_xor_sync(0xFFFFFFFF, p0, 2);
            p1 += __shfl_xor_sync(0xFFFFFFFF, p1, 1);
            p1 += __shfl_xor_sync(0xFFFFFFFF, p1, 2);
            if (t4 == 0) {
                spart[row_lo * 4 + warp_n] = p0;
                spart[(row_lo + 8) * 4 + warp_n] = p1;
            }
        }
        __syncthreads();
        if (tid < 128) {
            const float v = spart[tid * 4 + 0] + spart[tid * 4 + 1]
                          + spart[tid * 4 + 2] + spart[tid * 4 + 3];
            pred[(size_t)(m0 + tid) * CELL + ntile] = v;
        }
    }
}

// ---------------------------------------------------------------------------
// t[b,r] = sum_j V[b,j,r] * x[b,j]  (float4 vectorized)
// ---------------------------------------------------------------------------
__global__ void compute_t_k(const float* __restrict__ v, const float* __restrict__ x,
                            float* __restrict__ t)
{
    const int b = blockIdx.x;
    const int tid = threadIdx.x;
    __shared__ float sx[CELL];
    __shared__ float red[16][68];
    for (int j = tid; j < CELL; j += 256) sx[j] = x[(size_t)b * CELL + j];
    __syncthreads();
    const int rq = tid & 15;            // r-quad: r = rq*4 .. +3
    const int jg = tid >> 4;            // 16 j groups
    const float* vb = v + (size_t)b * HALF;
    float4 a = make_float4(0.f, 0.f, 0.f, 0.f);
    for (int j = jg; j < CELL; j += 16) {
        float4 w = *(const float4*)(vb + j * 64 + rq * 4);
        const float xx = sx[j];
        a.x += w.x * xx; a.y += w.y * xx; a.z += w.z * xx; a.w += w.w * xx;
    }
    *(float4*)&red[jg][rq * 4] = a;
    __syncthreads();
    if (tid < 64) {
        float s = 0.f;
        #pragma unroll
        for (int gg = 0; gg < 16; gg++) s += red[gg][tid];
        t[b * RANK + tid] = s;
    }
}

// ---------------------------------------------------------------------------
// launch
// ---------------------------------------------------------------------------
extern "C" void kernel_launch(void* const* d_in, const int* in_sizes, int n_in,
                              void* d_out, int out_size)
{
    const float* x     = (const float*)d_in[0];
    const float* seq   = (const float*)d_in[1];
    const float* W_dna = (const float*)d_in[2];
    const float* b_dna = (const float*)d_in[3];
    const float* W_hyp = (const float*)d_in[4];
    const float* b_hyp = (const float*)d_in[5];
    float* out = (float*)d_out;

    float *p_part, *p_v, *p_t;
    __half *p_Ah, *p_Al, *p_Bh;
    cudaGetSymbolAddress((void**)&p_part, g_part);
    cudaGetSymbolAddress((void**)&p_Ah, g_Ah);
    cudaGetSymbolAddress((void**)&p_Al, g_Al);
    cudaGetSymbolAddress((void**)&p_Bh, g_Bh);
    cudaGetSymbolAddress((void**)&p_v, g_v);
    cudaGetSymbolAddress((void**)&p_t, g_t);

    cudaFuncSetAttribute(gemm_mma_k, cudaFuncAttributeMaxDynamicSharedMemorySize, GEMM2_SMEM);

    // W_hyper -> transposed fp16 [98304, 256]
    {
        dim3 grid(NW / 64, DF / 64);
        transpose_convert_k<<<grid, 256>>>(W_hyp, p_Bh);
    }
    // GEMM1 split-K + epilogue (bias, relu, fp16 hi/lo)
    {
        dim3 grid(DF / 128, BDIM / 128, KSPLIT1);
        sgemm_k<<<grid, 256>>>(seq, W_dna, p_part, BDIM, DF, KDNA);
    }
    reduce_relu_convert_k<<<(BDIM * DF) / 256, 256>>>(p_part, b_dna, p_Ah, p_Al);

    // V-GEMM: 64-col n-tiles [768, 1536) -> g_v (+bias)
    {
        dim3 grid(BDIM / 128, 768);
        gemm_mma_k<<<grid, 256, GEMM2_SMEM>>>(p_Ah, p_Al, p_Bh, b_hyp,
                                              nullptr, p_v, nullptr, 768);
    }
    // t = V^T x
    compute_t_k<<<BDIM, 256>>>(p_v, x, p_t);

    // U-GEMM: 64-col n-tiles [0, 768) fused with t-contraction -> out
    {
        dim3 grid(BDIM / 128, 768);
        gemm_mma_k<<<grid, 256, GEMM2_SMEM>>>(p_Ah, p_Al, p_Bh, b_hyp,
                                              p_t, nullptr, out, 0);
    }
}

// round 9
// speedup vs baseline: 1.1830x; 1.1830x over previous
#include <cuda_runtime.h>
#include <cuda_fp16.h>
#include <cstdint>
#include <cstddef>

#define BDIM   512
#define CELL   768
#define RANK   64
#define DF     256
#define KDNA   4000
#define NW     98304
#define HALF   49152
#define KSPLIT1 10

// GEMM2 tiling: CTA = 128m x 128n, K-chunk 32, 8 stages, double-buffered
#define KCH    32
#define NSTG   8
#define LDA    40                        // smem stride (fp16): 80B rows, conflict-free ldmatrix
#define A_TILE (128 * LDA * 2)           // 10240 bytes (one of Ah/Al/B)
#define OFF_A(buf) ((buf) * 2 * A_TILE)  // Ah at +0, Al at +A_TILE
#define OFF_B(buf) (4 * A_TILE + (buf) * A_TILE)
#define GEMM2_SMEM (6 * A_TILE)          // 61440

// ---------------------------------------------------------------------------
// asm helpers (all proven in R5/R8)
// ---------------------------------------------------------------------------
__device__ __forceinline__ void mma_f16(float c[4],
                                        uint32_t a0, uint32_t a1, uint32_t a2, uint32_t a3,
                                        uint32_t b0, uint32_t b1)
{
    asm volatile(
        "mma.sync.aligned.m16n8k16.row.col.f32.f16.f16.f32 "
        "{%0,%1,%2,%3}, {%4,%5,%6,%7}, {%8,%9}, {%0,%1,%2,%3};"
        : "+f"(c[0]), "+f"(c[1]), "+f"(c[2]), "+f"(c[3])
        : "r"(a0), "r"(a1), "r"(a2), "r"(a3), "r"(b0), "r"(b1));
}
__device__ __forceinline__ uint32_t smem_u32(const void* p) {
    uint32_t a;
    asm("{ .reg .u64 t; cvta.to.shared.u64 t, %1; cvt.u32.u64 %0, t; }" : "=r"(a) : "l"(p));
    return a;
}
#define LDMX4(r0, r1, r2, r3, addr) \
    asm volatile("ldmatrix.sync.aligned.m8n8.x4.shared.b16 {%0,%1,%2,%3}, [%4];" \
                 : "=r"(r0), "=r"(r1), "=r"(r2), "=r"(r3) : "r"(addr))
#define LDMX2(r0, r1, addr) \
    asm volatile("ldmatrix.sync.aligned.m8n8.x2.shared.b16 {%0,%1}, [%2];" \
                 : "=r"(r0), "=r"(r1) : "r"(addr))
#define CP_ASYNC16(dst, src) \
    asm volatile("cp.async.cg.shared.global [%0], [%1], 16;" :: "r"(dst), "l"(src))
#define CP_COMMIT() asm volatile("cp.async.commit_group;" ::: "memory")
#define CP_WAIT1()  asm volatile("cp.async.wait_group 1;" ::: "memory")
#define CP_WAIT0()  asm volatile("cp.async.wait_group 0;" ::: "memory")

// ---------------------------------------------------------------------------
// device scratch
// ---------------------------------------------------------------------------
__device__ float g_part[KSPLIT1 * BDIM * DF];
__device__ __align__(256) __half g_Ah[BDIM * DF];
__device__ __align__(256) __half g_Al[BDIM * DF];
__device__ __align__(256) __half g_Bh[(size_t)NW * DF];   // W_hyper^T fp16 [n][k]
__device__ float g_v[(size_t)BDIM * HALF];
__device__ float g_t[BDIM * RANK];

// ---------------------------------------------------------------------------
// GEMM1: SIMT 128x128x8 SGEMM, split-K partials (proven)
// ---------------------------------------------------------------------------
__global__ void __launch_bounds__(256, 2)
sgemm_k(const float* __restrict__ A, const float* __restrict__ Bmat,
        float* __restrict__ C, int M, int N, int K)
{
    const int bn = blockIdx.x, bm = blockIdx.y, slice = blockIdx.z;
    const int kPer = K / gridDim.z;
    const int k0base = slice * kPer;

    __shared__ float As[8][128];
    __shared__ float Bs[8][128];

    const int tid = threadIdx.x;
    const int aRow = tid >> 1, aK4 = (tid & 1) * 4;
    const int bK = tid >> 5, bN4 = (tid & 31) * 4;
    const int tx = tid & 15, ty = tid >> 4;

    float acc[8][8];
    #pragma unroll
    for (int i = 0; i < 8; i++)
        #pragma unroll
        for (int j = 0; j < 8; j++) acc[i][j] = 0.f;

    const float* Aptr = A + (size_t)(bm * 128 + aRow) * K + k0base + aK4;
    const float* Bptr = Bmat + (size_t)(k0base + bK) * N + (size_t)bn * 128 + bN4;

    const int nsteps = kPer / 8;
    for (int kt = 0; kt < nsteps; kt++) {
        float4 av = *(const float4*)(Aptr);
        float4 bv = *(const float4*)(Bptr);
        As[aK4 + 0][aRow] = av.x; As[aK4 + 1][aRow] = av.y;
        As[aK4 + 2][aRow] = av.z; As[aK4 + 3][aRow] = av.w;
        *(float4*)&Bs[bK][bN4] = bv;
        __syncthreads();
        #pragma unroll
        for (int k = 0; k < 8; k++) {
            float af[8], bf[8];
            #pragma unroll
            for (int i = 0; i < 8; i++) af[i] = As[k][ty * 8 + i];
            #pragma unroll
            for (int j = 0; j < 8; j++) bf[j] = Bs[k][tx * 8 + j];
            #pragma unroll
            for (int i = 0; i < 8; i++)
                #pragma unroll
                for (int j = 0; j < 8; j++) acc[i][j] += af[i] * bf[j];
        }
        __syncthreads();
        Aptr += 8;
        Bptr += (size_t)8 * N;
    }
    float* Cbase = C + (size_t)slice * M * N;
    #pragma unroll
    for (int i = 0; i < 8; i++) {
        const int row = bm * 128 + ty * 8 + i;
        #pragma unroll
        for (int j = 0; j < 8; j += 4) {
            const int col = bn * 128 + tx * 8 + j;
            float4 v = make_float4(acc[i][j], acc[i][j+1], acc[i][j+2], acc[i][j+3]);
            *(float4*)(Cbase + (size_t)row * N + col) = v;
        }
    }
}

// ---------------------------------------------------------------------------
// reduce split-K + bias + relu -> fp16 hi/lo split of A
// ---------------------------------------------------------------------------
__global__ void reduce_relu_convert_k(const float* __restrict__ part,
                                      const float* __restrict__ bias,
                                      __half* __restrict__ Ah,
                                      __half* __restrict__ Al)
{
    const int i = blockIdx.x * 256 + threadIdx.x;
    float s = bias[i & (DF - 1)];
    #pragma unroll
    for (int sl = 0; sl < KSPLIT1; sl++) s += part[sl * (BDIM * DF) + i];
    s = fmaxf(s, 0.f);
    __half h = __float2half_rn(s);
    Ah[i] = h;
    Al[i] = __float2half_rn(s - __half2float(h));
}

// ---------------------------------------------------------------------------
// W_hyper [256, 98304] fp32 -> transposed fp16 [98304, 256]
// ---------------------------------------------------------------------------
__global__ void __launch_bounds__(256)
transpose_convert_k(const float* __restrict__ W, __half* __restrict__ Bh)
{
    __shared__ float s[64][65];
    const int n0 = blockIdx.x * 64, k0 = blockIdx.y * 64;
    const int t = threadIdx.x;
    {
        const int nn = t & 63, kk = t >> 6;
        #pragma unroll
        for (int p = 0; p < 16; p++) {
            int k = kk + p * 4;
            s[k][nn] = W[(size_t)(k0 + k) * NW + n0 + nn];
        }
    }
    __syncthreads();
    const int n = t >> 2, su = (t & 3) * 16;
    __align__(16) __half hi[16];
    #pragma unroll
    for (int i = 0; i < 16; i++)
        hi[i] = __float2half_rn(s[su + i][n]);
    const size_t o = (size_t)(n0 + n) * DF + k0 + su;
    *(int4*)(Bh + o)     = *(int4*)hi;
    *(int4*)(Bh + o + 8) = *(int4*)(hi + 8);
}

// ---------------------------------------------------------------------------
// fp16 2-term mma GEMM: C[128m x 128n] = A[128,256] @ B[128rows,256]^T
//   D = Ah*B + Al*B   (A exact to 22 bits, B single fp16)
// cp.async double-buffered (A hi/lo + B per stage).
// V mode (pred==nullptr): C+bias -> vout.  U mode: contract with t -> pred.
// ---------------------------------------------------------------------------
__global__ void __launch_bounds__(256, 2)
gemm_mma_k(const __half* __restrict__ Ahg, const __half* __restrict__ Alg,
           const __half* __restrict__ Bhg, const float* __restrict__ bias,
           const float* __restrict__ tvec, float* __restrict__ vout,
           float* __restrict__ pred, int ntile0)
{
    extern __shared__ char smem[];
    const uint32_t sb = smem_u32(smem);
    const int tid = threadIdx.x, wid = tid >> 5, lane = tid & 31;
    const int bm = blockIdx.x;                 // fast dim -> B tile L2 reuse
    const int ntile = ntile0 + blockIdx.y;
    const int m0 = bm * 128, nrow0 = ntile * 128;
    const int warp_m = wid & 1, warp_n = wid >> 1;   // 2x4 warps: 64m x 32n each
    const int g = lane >> 2, t4 = lane & 3;

    float acc[4][4][4];
    #pragma unroll
    for (int mf = 0; mf < 4; mf++)
        #pragma unroll
        for (int nf = 0; nf < 4; nf++)
            #pragma unroll
            for (int c = 0; c < 4; c++) acc[mf][nf][c] = 0.f;

    const int a_row = warp_m * 64 + (lane & 15);
    const int a_koff = (lane >> 4) * 8;
    const int b_row = lane & 7;
    const int b_koff = ((lane >> 3) & 1) * 8;

    const __half* Asrc_h = Ahg + (size_t)m0 * DF;
    const __half* Asrc_l = Alg + (size_t)m0 * DF;
    const __half* Bsrc   = Bhg + (size_t)nrow0 * DF;

    auto load_stage = [&](int buf, int k0) {
        // each tile: 128 rows x 32 k fp16 = 512 int4 transfers
        #pragma unroll
        for (int p = 0; p < 2; p++) {
            const int c = tid + p * 256;
            const int row = c >> 2, j = c & 3;
            const uint32_t so = (uint32_t)(row * LDA + j * 8) * 2;
            const size_t go = (size_t)row * DF + k0 + j * 8;
            CP_ASYNC16(sb + OFF_A(buf) + so, Asrc_h + go);
            CP_ASYNC16(sb + OFF_A(buf) + A_TILE + so, Asrc_l + go);
            CP_ASYNC16(sb + OFF_B(buf) + so, Bsrc + go);
        }
    };

    auto compute = [&](int buf) {
        const uint32_t ah_base = sb + OFF_A(buf);
        const uint32_t al_base = ah_base + A_TILE;
        const uint32_t b_base  = sb + OFF_B(buf);
        #pragma unroll
        for (int ks = 0; ks < 2; ks++) {
            uint32_t bh[4][2];
            #pragma unroll
            for (int nf = 0; nf < 4; nf++) {
                const uint32_t bo = (uint32_t)((warp_n * 32 + nf * 8 + b_row) * LDA
                                               + ks * 16 + b_koff) * 2;
                LDMX2(bh[nf][0], bh[nf][1], b_base + bo);
            }
            #pragma unroll
            for (int mf = 0; mf < 4; mf++) {
                uint32_t ah[4], al[4];
                const uint32_t so = (uint32_t)((a_row + mf * 16) * LDA + ks * 16 + a_koff) * 2;
                LDMX4(ah[0], ah[1], ah[2], ah[3], ah_base + so);
                LDMX4(al[0], al[1], al[2], al[3], al_base + so);
                #pragma unroll
                for (int nf = 0; nf < 4; nf++) {
                    mma_f16(acc[mf][nf], ah[0], ah[1], ah[2], ah[3], bh[nf][0], bh[nf][1]);
                    mma_f16(acc[mf][nf], al[0], al[1], al[2], al[3], bh[nf][0], bh[nf][1]);
                }
            }
        }
    };

    load_stage(0, 0);
    CP_COMMIT();
    for (int s = 0; s < NSTG; s++) {
        if (s + 1 < NSTG) {
            load_stage((s + 1) & 1, (s + 1) * KCH);
            CP_COMMIT();
            CP_WAIT1();
        } else {
            CP_WAIT0();
        }
        __syncthreads();          // stage s data ready
        compute(s & 1);
        __syncthreads();          // free buf before next overwrite
    }

    // ------------------------- epilogue (R5-proven) -------------------------
    if (pred == nullptr) {
        // V mode: C + bias -> vout
        #pragma unroll
        for (int mf = 0; mf < 4; mf++) {
            const int row = warp_m * 64 + mf * 16 + g;
            #pragma unroll
            for (int nf = 0; nf < 4; nf++) {
                const int col = warp_n * 32 + nf * 8 + 2 * t4;
                const float b0 = bias[nrow0 + col], b1 = bias[nrow0 + col + 1];
                const size_t base = (size_t)(m0 + row) * HALF + (nrow0 - HALF) + col;
                float2 v0 = make_float2(acc[mf][nf][0] + b0, acc[mf][nf][1] + b1);
                float2 v1 = make_float2(acc[mf][nf][2] + b0, acc[mf][nf][3] + b1);
                *(float2*)&vout[base] = v0;
                *(float2*)&vout[base + (size_t)8 * HALF] = v1;
            }
        }
    } else {
        // U mode: pred[b, i] = sum_col (C+bias) * t[b, col&63]
        float* spart = (float*)smem;
        #pragma unroll
        for (int mf = 0; mf < 4; mf++) {
            const int row_lo = warp_m * 64 + mf * 16 + g;
            float p0 = 0.f, p1 = 0.f;
            const float* t0p = tvec + (size_t)(m0 + row_lo) * RANK;
            const float* t1p = tvec + (size_t)(m0 + row_lo + 8) * RANK;
            #pragma unroll
            for (int nf = 0; nf < 4; nf++) {
                const int col = warp_n * 32 + nf * 8 + 2 * t4;
                const int r = col & 63;
                const float b0 = bias[nrow0 + col], b1 = bias[nrow0 + col + 1];
                p0 += (acc[mf][nf][0] + b0) * t0p[r] + (acc[mf][nf][1] + b1) * t0p[r + 1];
                p1 += (acc[mf][nf][2] + b0) * t1p[r] + (acc[mf][nf][3] + b1) * t1p[r + 1];
            }
            p0 += __shfl_xor_sync(0xFFFFFFFF, p0, 1);
            p0 += __shfl_xor_sync(0xFFFFFFFF, p0, 2);
            p1 += __shfl_xor_sync(0xFFFFFFFF, p1, 1);
            p1 += __shfl_xor_sync(0xFFFFFFFF, p1, 2);
            if (t4 == 0) {
                spart[row_lo * 4 + warp_n] = p0;
                spart[(row_lo + 8) * 4 + warp_n] = p1;
            }
        }
        __syncthreads();
        {
            const int row = tid >> 1, ih = tid & 1;
            const float v = spart[row * 4 + 2 * ih] + spart[row * 4 + 2 * ih + 1];
            pred[(size_t)(m0 + row) * CELL + 2 * ntile + ih] = v;
        }
    }
}

// ---------------------------------------------------------------------------
// t[b,r] = sum_j V[b,j,r] * x[b,j]  (float4 vectorized)
// ---------------------------------------------------------------------------
__global__ void compute_t_k(const float* __restrict__ v, const float* __restrict__ x,
                            float* __restrict__ t)
{
    const int b = blockIdx.x;
    const int tid = threadIdx.x;
    __shared__ float sx[CELL];
    __shared__ float red[16][68];
    for (int j = tid; j < CELL; j += 256) sx[j] = x[(size_t)b * CELL + j];
    __syncthreads();
    const int rq = tid & 15;
    const int jg = tid >> 4;
    const float* vb = v + (size_t)b * HALF;
    float4 a = make_float4(0.f, 0.f, 0.f, 0.f);
    for (int j = jg; j < CELL; j += 16) {
        float4 w = *(const float4*)(vb + j * 64 + rq * 4);
        const float xx = sx[j];
        a.x += w.x * xx; a.y += w.y * xx; a.z += w.z * xx; a.w += w.w * xx;
    }
    *(float4*)&red[jg][rq * 4] = a;
    __syncthreads();
    if (tid < 64) {
        float s = 0.f;
        #pragma unroll
        for (int gg = 0; gg < 16; gg++) s += red[gg][tid];
        t[b * RANK + tid] = s;
    }
}

// ---------------------------------------------------------------------------
// launch
// ---------------------------------------------------------------------------
extern "C" void kernel_launch(void* const* d_in, const int* in_sizes, int n_in,
                              void* d_out, int out_size)
{
    const float* x     = (const float*)d_in[0];
    const float* seq   = (const float*)d_in[1];
    const float* W_dna = (const float*)d_in[2];
    const float* b_dna = (const float*)d_in[3];
    const float* W_hyp = (const float*)d_in[4];
    const float* b_hyp = (const float*)d_in[5];
    float* out = (float*)d_out;

    float *p_part, *p_v, *p_t;
    __half *p_Ah, *p_Al, *p_Bh;
    cudaGetSymbolAddress((void**)&p_part, g_part);
    cudaGetSymbolAddress((void**)&p_Ah, g_Ah);
    cudaGetSymbolAddress((void**)&p_Al, g_Al);
    cudaGetSymbolAddress((void**)&p_Bh, g_Bh);
    cudaGetSymbolAddress((void**)&p_v, g_v);
    cudaGetSymbolAddress((void**)&p_t, g_t);

    cudaFuncSetAttribute(gemm_mma_k, cudaFuncAttributeMaxDynamicSharedMemorySize, GEMM2_SMEM);

    // W_hyper -> transposed fp16 [98304, 256]
    {
        dim3 grid(NW / 64, DF / 64);
        transpose_convert_k<<<grid, 256>>>(W_hyp, p_Bh);
    }
    // GEMM1 split-K + epilogue (bias, relu, fp16 hi/lo)
    {
        dim3 grid(DF / 128, BDIM / 128, KSPLIT1);
        sgemm_k<<<grid, 256>>>(seq, W_dna, p_part, BDIM, DF, KDNA);
    }
    reduce_relu_convert_k<<<(BDIM * DF) / 256, 256>>>(p_part, b_dna, p_Ah, p_Al);

    // V-GEMM: 128-col n-tiles [384, 768) -> g_v (+bias)
    {
        dim3 grid(BDIM / 128, 384);
        gemm_mma_k<<<grid, 256, GEMM2_SMEM>>>(p_Ah, p_Al, p_Bh, b_hyp,
                                              nullptr, p_v, nullptr, 384);
    }
    // t = V^T x
    compute_t_k<<<BDIM, 256>>>(p_v, x, p_t);

    // U-GEMM: 128-col n-tiles [0, 384) fused with t-contraction -> out
    {
        dim3 grid(BDIM / 128, 384);
        gemm_mma_k<<<grid, 256, GEMM2_SMEM>>>(p_Ah, p_Al, p_Bh, b_hyp,
                                              p_t, nullptr, out, 0);
    }
}

// round 10
// speedup vs baseline: 1.3682x; 1.1566x over previous
#include <cuda_runtime.h>
#include <cuda_fp16.h>
#include <cstdint>
#include <cstddef>

#define BDIM   512
#define CELL   768
#define RANK   64
#define DF     256
#define KDNA   4000
#define NW     98304
#define HALF   49152
#define KSPLIT1 20

// GEMM2 tiling: CTA = 128m x 128n, K-chunk 32, 8 stages, 3-buffer pipeline
#define KCH    32
#define NSTG   8
#define LDA    40                        // smem stride (fp16): 80B rows, conflict-free ldmatrix
#define A_TILE (128 * LDA * 2)           // 10240 bytes (one of Ah/Al/B)
#define OFF_A(buf) ((buf) * 2 * A_TILE)  // Ah at +0, Al at +A_TILE
#define OFF_B(buf) (6 * A_TILE + (buf) * A_TILE)
#define GEMM2_SMEM (9 * A_TILE)          // 92160

// ---------------------------------------------------------------------------
// asm helpers (proven R5/R8/R9)
// ---------------------------------------------------------------------------
__device__ __forceinline__ void mma_f16(float c[4],
                                        uint32_t a0, uint32_t a1, uint32_t a2, uint32_t a3,
                                        uint32_t b0, uint32_t b1)
{
    asm volatile(
        "mma.sync.aligned.m16n8k16.row.col.f32.f16.f16.f32 "
        "{%0,%1,%2,%3}, {%4,%5,%6,%7}, {%8,%9}, {%0,%1,%2,%3};"
        : "+f"(c[0]), "+f"(c[1]), "+f"(c[2]), "+f"(c[3])
        : "r"(a0), "r"(a1), "r"(a2), "r"(a3), "r"(b0), "r"(b1));
}
__device__ __forceinline__ uint32_t smem_u32(const void* p) {
    uint32_t a;
    asm("{ .reg .u64 t; cvta.to.shared.u64 t, %1; cvt.u32.u64 %0, t; }" : "=r"(a) : "l"(p));
    return a;
}
#define LDMX4(r0, r1, r2, r3, addr) \
    asm volatile("ldmatrix.sync.aligned.m8n8.x4.shared.b16 {%0,%1,%2,%3}, [%4];" \
                 : "=r"(r0), "=r"(r1), "=r"(r2), "=r"(r3) : "r"(addr))
#define LDMX2(r0, r1, addr) \
    asm volatile("ldmatrix.sync.aligned.m8n8.x2.shared.b16 {%0,%1}, [%2];" \
                 : "=r"(r0), "=r"(r1) : "r"(addr))
#define CP_ASYNC16(dst, src) \
    asm volatile("cp.async.cg.shared.global [%0], [%1], 16;" :: "r"(dst), "l"(src))
#define CP_COMMIT() asm volatile("cp.async.commit_group;" ::: "memory")
#define CP_WAIT1()  asm volatile("cp.async.wait_group 1;" ::: "memory")
#define CP_WAIT0()  asm volatile("cp.async.wait_group 0;" ::: "memory")

// ---------------------------------------------------------------------------
// device scratch
// ---------------------------------------------------------------------------
__device__ float g_part[KSPLIT1 * BDIM * DF];
__device__ __align__(256) __half g_Ah[BDIM * DF];
__device__ __align__(256) __half g_Al[BDIM * DF];
__device__ __align__(256) __half g_Bh[(size_t)NW * DF];   // W_hyper^T fp16 [n][k]
__device__ float g_v[(size_t)BDIM * HALF];
__device__ float g_t[BDIM * RANK];

// ---------------------------------------------------------------------------
// GEMM1: SIMT 128x128x8 SGEMM, split-K partials
// ---------------------------------------------------------------------------
__global__ void __launch_bounds__(256, 2)
sgemm_k(const float* __restrict__ A, const float* __restrict__ Bmat,
        float* __restrict__ C, int M, int N, int K)
{
    const int bn = blockIdx.x, bm = blockIdx.y, slice = blockIdx.z;
    const int kPer = K / gridDim.z;
    const int k0base = slice * kPer;

    __shared__ float As[8][128];
    __shared__ float Bs[8][128];

    const int tid = threadIdx.x;
    const int aRow = tid >> 1, aK4 = (tid & 1) * 4;
    const int bK = tid >> 5, bN4 = (tid & 31) * 4;
    const int tx = tid & 15, ty = tid >> 4;

    float acc[8][8];
    #pragma unroll
    for (int i = 0; i < 8; i++)
        #pragma unroll
        for (int j = 0; j < 8; j++) acc[i][j] = 0.f;

    const float* Aptr = A + (size_t)(bm * 128 + aRow) * K + k0base + aK4;
    const float* Bptr = Bmat + (size_t)(k0base + bK) * N + (size_t)bn * 128 + bN4;

    const int nsteps = kPer / 8;
    for (int kt = 0; kt < nsteps; kt++) {
        float4 av = *(const float4*)(Aptr);
        float4 bv = *(const float4*)(Bptr);
        As[aK4 + 0][aRow] = av.x; As[aK4 + 1][aRow] = av.y;
        As[aK4 + 2][aRow] = av.z; As[aK4 + 3][aRow] = av.w;
        *(float4*)&Bs[bK][bN4] = bv;
        __syncthreads();
        #pragma unroll
        for (int k = 0; k < 8; k++) {
            float af[8], bf[8];
            #pragma unroll
            for (int i = 0; i < 8; i++) af[i] = As[k][ty * 8 + i];
            #pragma unroll
            for (int j = 0; j < 8; j++) bf[j] = Bs[k][tx * 8 + j];
            #pragma unroll
            for (int i = 0; i < 8; i++)
                #pragma unroll
                for (int j = 0; j < 8; j++) acc[i][j] += af[i] * bf[j];
        }
        __syncthreads();
        Aptr += 8;
        Bptr += (size_t)8 * N;
    }
    float* Cbase = C + (size_t)slice * M * N;
    #pragma unroll
    for (int i = 0; i < 8; i++) {
        const int row = bm * 128 + ty * 8 + i;
        #pragma unroll
        for (int j = 0; j < 8; j += 4) {
            const int col = bn * 128 + tx * 8 + j;
            float4 v = make_float4(acc[i][j], acc[i][j+1], acc[i][j+2], acc[i][j+3]);
            *(float4*)(Cbase + (size_t)row * N + col) = v;
        }
    }
}

// ---------------------------------------------------------------------------
// reduce split-K + bias + relu -> fp16 hi/lo split of A
// ---------------------------------------------------------------------------
__global__ void reduce_relu_convert_k(const float* __restrict__ part,
                                      const float* __restrict__ bias,
                                      __half* __restrict__ Ah,
                                      __half* __restrict__ Al)
{
    const int i = blockIdx.x * 256 + threadIdx.x;
    float s = bias[i & (DF - 1)];
    #pragma unroll
    for (int sl = 0; sl < KSPLIT1; sl++) s += part[sl * (BDIM * DF) + i];
    s = fmaxf(s, 0.f);
    __half h = __float2half_rn(s);
    Ah[i] = h;
    Al[i] = __float2half_rn(s - __half2float(h));
}

// ---------------------------------------------------------------------------
// W_hyper [256, 98304] fp32 -> transposed fp16 [98304, 256]
// ---------------------------------------------------------------------------
__global__ void __launch_bounds__(256)
transpose_convert_k(const float* __restrict__ W, __half* __restrict__ Bh)
{
    __shared__ float s[64][65];
    const int n0 = blockIdx.x * 64, k0 = blockIdx.y * 64;
    const int t = threadIdx.x;
    {
        const int nn = t & 63, kk = t >> 6;
        #pragma unroll
        for (int p = 0; p < 16; p++) {
            int k = kk + p * 4;
            s[k][nn] = W[(size_t)(k0 + k) * NW + n0 + nn];
        }
    }
    __syncthreads();
    const int n = t >> 2, su = (t & 3) * 16;
    __align__(16) __half hi[16];
    #pragma unroll
    for (int i = 0; i < 16; i++)
        hi[i] = __float2half_rn(s[su + i][n]);
    const size_t o = (size_t)(n0 + n) * DF + k0 + su;
    *(int4*)(Bh + o)     = *(int4*)hi;
    *(int4*)(Bh + o + 8) = *(int4*)(hi + 8);
}

// ---------------------------------------------------------------------------
// fp16 2-term mma GEMM: C[128m x 128n] = A[128,256] @ B[128rows,256]^T
//   D = Ah*B + Al*B.  3-stage cp.async pipeline, ONE sync per stage.
// V mode (pred==nullptr): C+bias -> vout.  U mode: contract with t -> pred.
// ---------------------------------------------------------------------------
__global__ void __launch_bounds__(256, 2)
gemm_mma_k(const __half* __restrict__ Ahg, const __half* __restrict__ Alg,
           const __half* __restrict__ Bhg, const float* __restrict__ bias,
           const float* __restrict__ tvec, float* __restrict__ vout,
           float* __restrict__ pred, int ntile0)
{
    extern __shared__ char smem[];
    const uint32_t sb = smem_u32(smem);
    const int tid = threadIdx.x, wid = tid >> 5, lane = tid & 31;
    const int bm = blockIdx.x;                 // fast dim -> B tile L2 reuse
    const int ntile = ntile0 + blockIdx.y;
    const int m0 = bm * 128, nrow0 = ntile * 128;
    const int warp_m = wid & 1, warp_n = wid >> 1;   // 2x4 warps: 64m x 32n each
    const int g = lane >> 2, t4 = lane & 3;

    float acc[4][4][4];
    #pragma unroll
    for (int mf = 0; mf < 4; mf++)
        #pragma unroll
        for (int nf = 0; nf < 4; nf++)
            #pragma unroll
            for (int c = 0; c < 4; c++) acc[mf][nf][c] = 0.f;

    const int a_row = warp_m * 64 + (lane & 15);
    const int a_koff = (lane >> 4) * 8;
    const int b_row = lane & 7;
    const int b_koff = ((lane >> 3) & 1) * 8;

    const __half* Asrc_h = Ahg + (size_t)m0 * DF;
    const __half* Asrc_l = Alg + (size_t)m0 * DF;
    const __half* Bsrc   = Bhg + (size_t)nrow0 * DF;

    auto load_stage = [&](int buf, int k0) {
        #pragma unroll
        for (int p = 0; p < 2; p++) {
            const int c = tid + p * 256;
            const int row = c >> 2, j = c & 3;
            const uint32_t so = (uint32_t)(row * LDA + j * 8) * 2;
            const size_t go = (size_t)row * DF + k0 + j * 8;
            CP_ASYNC16(sb + OFF_A(buf) + so, Asrc_h + go);
            CP_ASYNC16(sb + OFF_A(buf) + A_TILE + so, Asrc_l + go);
            CP_ASYNC16(sb + OFF_B(buf) + so, Bsrc + go);
        }
    };

    auto compute = [&](int buf) {
        const uint32_t ah_base = sb + OFF_A(buf);
        const uint32_t al_base = ah_base + A_TILE;
        const uint32_t b_base  = sb + OFF_B(buf);
        #pragma unroll
        for (int ks = 0; ks < 2; ks++) {
            uint32_t bh[4][2];
            #pragma unroll
            for (int nf = 0; nf < 4; nf++) {
                const uint32_t bo = (uint32_t)((warp_n * 32 + nf * 8 + b_row) * LDA
                                               + ks * 16 + b_koff) * 2;
                LDMX2(bh[nf][0], bh[nf][1], b_base + bo);
            }
            #pragma unroll
            for (int mf = 0; mf < 4; mf++) {
                uint32_t ah[4], al[4];
                const uint32_t so = (uint32_t)((a_row + mf * 16) * LDA + ks * 16 + a_koff) * 2;
                LDMX4(ah[0], ah[1], ah[2], ah[3], ah_base + so);
                LDMX4(al[0], al[1], al[2], al[3], al_base + so);
                #pragma unroll
                for (int nf = 0; nf < 4; nf++) {
                    mma_f16(acc[mf][nf], ah[0], ah[1], ah[2], ah[3], bh[nf][0], bh[nf][1]);
                    mma_f16(acc[mf][nf], al[0], al[1], al[2], al[3], bh[nf][0], bh[nf][1]);
                }
            }
        }
    };

    // --- 3-stage pipeline, one barrier per stage ---
    load_stage(0, 0);
    CP_COMMIT();
    load_stage(1, KCH);
    CP_COMMIT();
    #pragma unroll
    for (int s = 0; s < NSTG; s++) {
        if (s + 1 < NSTG) CP_WAIT1(); else CP_WAIT0();  // stage s landed
        __syncthreads();        // all threads see stage s; compute(s-1) done -> buf (s-1)%3 free
        if (s + 2 < NSTG) {
            load_stage((s + 2) % 3, (s + 2) * KCH);
            CP_COMMIT();
        }
        compute(s % 3);
    }
    __syncthreads();            // epilogue reuses smem (U mode)

    // ------------------------- epilogue -------------------------
    if (pred == nullptr) {
        // V mode: C + bias -> vout
        #pragma unroll
        for (int mf = 0; mf < 4; mf++) {
            const int row = warp_m * 64 + mf * 16 + g;
            #pragma unroll
            for (int nf = 0; nf < 4; nf++) {
                const int col = warp_n * 32 + nf * 8 + 2 * t4;
                const float b0 = bias[nrow0 + col], b1 = bias[nrow0 + col + 1];
                const size_t base = (size_t)(m0 + row) * HALF + (nrow0 - HALF) + col;
                float2 v0 = make_float2(acc[mf][nf][0] + b0, acc[mf][nf][1] + b1);
                float2 v1 = make_float2(acc[mf][nf][2] + b0, acc[mf][nf][3] + b1);
                *(float2*)&vout[base] = v0;
                *(float2*)&vout[base + (size_t)8 * HALF] = v1;
            }
        }
    } else {
        // U mode: pred[b, i] = sum_col (C+bias) * t[b, col&63]
        float* spart = (float*)smem;
        #pragma unroll
        for (int mf = 0; mf < 4; mf++) {
            const int row_lo = warp_m * 64 + mf * 16 + g;
            float p0 = 0.f, p1 = 0.f;
            const float* t0p = tvec + (size_t)(m0 + row_lo) * RANK;
            const float* t1p = tvec + (size_t)(m0 + row_lo + 8) * RANK;
            #pragma unroll
            for (int nf = 0; nf < 4; nf++) {
                const int col = warp_n * 32 + nf * 8 + 2 * t4;
                const int r = col & 63;
                const float b0 = bias[nrow0 + col], b1 = bias[nrow0 + col + 1];
                p0 += (acc[mf][nf][0] + b0) * t0p[r] + (acc[mf][nf][1] + b1) * t0p[r + 1];
                p1 += (acc[mf][nf][2] + b0) * t1p[r] + (acc[mf][nf][3] + b1) * t1p[r + 1];
            }
            p0 += __shfl_xor_sync(0xFFFFFFFF, p0, 1);
            p0 += __shfl_xor_sync(0xFFFFFFFF, p0, 2);
            p1 += __shfl_xor_sync(0xFFFFFFFF, p1, 1);
            p1 += __shfl_xor_sync(0xFFFFFFFF, p1, 2);
            if (t4 == 0) {
                spart[row_lo * 4 + warp_n] = p0;
                spart[(row_lo + 8) * 4 + warp_n] = p1;
            }
        }
        __syncthreads();
        {
            const int row = tid >> 1, ih = tid & 1;
            const float v = spart[row * 4 + 2 * ih] + spart[row * 4 + 2 * ih + 1];
            pred[(size_t)(m0 + row) * CELL + 2 * ntile + ih] = v;
        }
    }
}

// ---------------------------------------------------------------------------
// t[b,r] = sum_j V[b,j,r] * x[b,j]  (float4 vectorized)
// ---------------------------------------------------------------------------
__global__ void compute_t_k(const float* __restrict__ v, const float* __restrict__ x,
                            float* __restrict__ t)
{
    const int b = blockIdx.x;
    const int tid = threadIdx.x;
    __shared__ float sx[CELL];
    __shared__ float red[16][68];
    for (int j = tid; j < CELL; j += 256) sx[j] = x[(size_t)b * CELL + j];
    __syncthreads();
    const int rq = tid & 15;
    const int jg = tid >> 4;
    const float* vb = v + (size_t)b * HALF;
    float4 a = make_float4(0.f, 0.f, 0.f, 0.f);
    for (int j = jg; j < CELL; j += 16) {
        float4 w = *(const float4*)(vb + j * 64 + rq * 4);
        const float xx = sx[j];
        a.x += w.x * xx; a.y += w.y * xx; a.z += w.z * xx; a.w += w.w * xx;
    }
    *(float4*)&red[jg][rq * 4] = a;
    __syncthreads();
    if (tid < 64) {
        float s = 0.f;
        #pragma unroll
        for (int gg = 0; gg < 16; gg++) s += red[gg][tid];
        t[b * RANK + tid] = s;
    }
}

// ---------------------------------------------------------------------------
// launch
// ---------------------------------------------------------------------------
extern "C" void kernel_launch(void* const* d_in, const int* in_sizes, int n_in,
                              void* d_out, int out_size)
{
    const float* x     = (const float*)d_in[0];
    const float* seq   = (const float*)d_in[1];
    const float* W_dna = (const float*)d_in[2];
    const float* b_dna = (const float*)d_in[3];
    const float* W_hyp = (const float*)d_in[4];
    const float* b_hyp = (const float*)d_in[5];
    float* out = (float*)d_out;

    float *p_part, *p_v, *p_t;
    __half *p_Ah, *p_Al, *p_Bh;
    cudaGetSymbolAddress((void**)&p_part, g_part);
    cudaGetSymbolAddress((void**)&p_Ah, g_Ah);
    cudaGetSymbolAddress((void**)&p_Al, g_Al);
    cudaGetSymbolAddress((void**)&p_Bh, g_Bh);
    cudaGetSymbolAddress((void**)&p_v, g_v);
    cudaGetSymbolAddress((void**)&p_t, g_t);

    cudaFuncSetAttribute(gemm_mma_k, cudaFuncAttributeMaxDynamicSharedMemorySize, GEMM2_SMEM);

    // W_hyper -> transposed fp16 [98304, 256]
    {
        dim3 grid(NW / 64, DF / 64);
        transpose_convert_k<<<grid, 256>>>(W_hyp, p_Bh);
    }
    // GEMM1 split-K + epilogue (bias, relu, fp16 hi/lo)
    {
        dim3 grid(DF / 128, BDIM / 128, KSPLIT1);
        sgemm_k<<<grid, 256>>>(seq, W_dna, p_part, BDIM, DF, KDNA);
    }
    reduce_relu_convert_k<<<(BDIM * DF) / 256, 256>>>(p_part, b_dna, p_Ah, p_Al);

    // V-GEMM: 128-col n-tiles [384, 768) -> g_v (+bias)
    {
        dim3 grid(BDIM / 128, 384);
        gemm_mma_k<<<grid, 256, GEMM2_SMEM>>>(p_Ah, p_Al, p_Bh, b_hyp,
                                              nullptr, p_v, nullptr, 384);
    }
    // t = V^T x
    compute_t_k<<<BDIM, 256>>>(p_v, x, p_t);

    // U-GEMM: 128-col n-tiles [0, 384) fused with t-contraction -> out
    {
        dim3 grid(BDIM / 128, 384);
        gemm_mma_k<<<grid, 256, GEMM2_SMEM>>>(p_Ah, p_Al, p_Bh, b_hyp,
                                              p_t, nullptr, out, 0);
    }
}

// round 11
// speedup vs baseline: 1.7189x; 1.2563x over previous
#include <cuda_runtime.h>
#include <cuda_fp16.h>
#include <cstdint>
#include <cstddef>

#define BDIM   512
#define CELL   768
#define RANK   64
#define DF     256
#define KDNA   4000
#define NW     98304
#define HALF   49152
#define KSPLIT1 20

// GEMM2 tiling: CTA = 128m x 128n, K-chunk 64, 4 stages, 3-buffer pipeline
#define KCH    64
#define NSTG   4
#define LDA    72                        // smem stride (fp16): 144B rows, conflict-free ldmatrix
#define A_TILE (128 * LDA * 2)           // 18432 bytes (one of Ah/B)
#define OFF_A(buf) ((buf) * A_TILE)
#define OFF_B(buf) (3 * A_TILE + (buf) * A_TILE)
#define GEMM2_SMEM (6 * A_TILE)          // 110592

// ---------------------------------------------------------------------------
// asm helpers (proven R5/R8/R9/R10)
// ---------------------------------------------------------------------------
__device__ __forceinline__ void mma_f16(float c[4],
                                        uint32_t a0, uint32_t a1, uint32_t a2, uint32_t a3,
                                        uint32_t b0, uint32_t b1)
{
    asm volatile(
        "mma.sync.aligned.m16n8k16.row.col.f32.f16.f16.f32 "
        "{%0,%1,%2,%3}, {%4,%5,%6,%7}, {%8,%9}, {%0,%1,%2,%3};"
        : "+f"(c[0]), "+f"(c[1]), "+f"(c[2]), "+f"(c[3])
        : "r"(a0), "r"(a1), "r"(a2), "r"(a3), "r"(b0), "r"(b1));
}
__device__ __forceinline__ uint32_t smem_u32(const void* p) {
    uint32_t a;
    asm("{ .reg .u64 t; cvta.to.shared.u64 t, %1; cvt.u32.u64 %0, t; }" : "=r"(a) : "l"(p));
    return a;
}
#define LDMX4(r0, r1, r2, r3, addr) \
    asm volatile("ldmatrix.sync.aligned.m8n8.x4.shared.b16 {%0,%1,%2,%3}, [%4];" \
                 : "=r"(r0), "=r"(r1), "=r"(r2), "=r"(r3) : "r"(addr))
#define LDMX2(r0, r1, addr) \
    asm volatile("ldmatrix.sync.aligned.m8n8.x2.shared.b16 {%0,%1}, [%2];" \
                 : "=r"(r0), "=r"(r1) : "r"(addr))
#define CP_ASYNC16(dst, src) \
    asm volatile("cp.async.cg.shared.global [%0], [%1], 16;" :: "r"(dst), "l"(src))
#define CP_COMMIT() asm volatile("cp.async.commit_group;" ::: "memory")
#define CP_WAIT1()  asm volatile("cp.async.wait_group 1;" ::: "memory")
#define CP_WAIT0()  asm volatile("cp.async.wait_group 0;" ::: "memory")

// ---------------------------------------------------------------------------
// device scratch
// ---------------------------------------------------------------------------
__device__ float g_part[KSPLIT1 * BDIM * DF];
__device__ __align__(256) __half g_Ah[BDIM * DF];
__device__ __align__(256) __half g_Bh[(size_t)NW * DF];   // W_hyper^T fp16 [n][k]
__device__ float g_v[(size_t)BDIM * HALF];
__device__ float g_t[BDIM * RANK];

// ---------------------------------------------------------------------------
// GEMM1: SIMT 128x128x8 SGEMM, split-K partials
// ---------------------------------------------------------------------------
__global__ void __launch_bounds__(256, 2)
sgemm_k(const float* __restrict__ A, const float* __restrict__ Bmat,
        float* __restrict__ C, int M, int N, int K)
{
    const int bn = blockIdx.x, bm = blockIdx.y, slice = blockIdx.z;
    const int kPer = K / gridDim.z;
    const int k0base = slice * kPer;

    __shared__ float As[8][128];
    __shared__ float Bs[8][128];

    const int tid = threadIdx.x;
    const int aRow = tid >> 1, aK4 = (tid & 1) * 4;
    const int bK = tid >> 5, bN4 = (tid & 31) * 4;
    const int tx = tid & 15, ty = tid >> 4;

    float acc[8][8];
    #pragma unroll
    for (int i = 0; i < 8; i++)
        #pragma unroll
        for (int j = 0; j < 8; j++) acc[i][j] = 0.f;

    const float* Aptr = A + (size_t)(bm * 128 + aRow) * K + k0base + aK4;
    const float* Bptr = Bmat + (size_t)(k0base + bK) * N + (size_t)bn * 128 + bN4;

    const int nsteps = kPer / 8;
    for (int kt = 0; kt < nsteps; kt++) {
        float4 av = *(const float4*)(Aptr);
        float4 bv = *(const float4*)(Bptr);
        As[aK4 + 0][aRow] = av.x; As[aK4 + 1][aRow] = av.y;
        As[aK4 + 2][aRow] = av.z; As[aK4 + 3][aRow] = av.w;
        *(float4*)&Bs[bK][bN4] = bv;
        __syncthreads();
        #pragma unroll
        for (int k = 0; k < 8; k++) {
            float af[8], bf[8];
            #pragma unroll
            for (int i = 0; i < 8; i++) af[i] = As[k][ty * 8 + i];
            #pragma unroll
            for (int j = 0; j < 8; j++) bf[j] = Bs[k][tx * 8 + j];
            #pragma unroll
            for (int i = 0; i < 8; i++)
                #pragma unroll
                for (int j = 0; j < 8; j++) acc[i][j] += af[i] * bf[j];
        }
        __syncthreads();
        Aptr += 8;
        Bptr += (size_t)8 * N;
    }
    float* Cbase = C + (size_t)slice * M * N;
    #pragma unroll
    for (int i = 0; i < 8; i++) {
        const int row = bm * 128 + ty * 8 + i;
        #pragma unroll
        for (int j = 0; j < 8; j += 4) {
            const int col = bn * 128 + tx * 8 + j;
            float4 v = make_float4(acc[i][j], acc[i][j+1], acc[i][j+2], acc[i][j+3]);
            *(float4*)(Cbase + (size_t)row * N + col) = v;
        }
    }
}

// ---------------------------------------------------------------------------
// reduce split-K + bias + relu -> fp16 A
// ---------------------------------------------------------------------------
__global__ void reduce_relu_convert_k(const float* __restrict__ part,
                                      const float* __restrict__ bias,
                                      __half* __restrict__ Ah)
{
    const int i = blockIdx.x * 256 + threadIdx.x;
    float s = bias[i & (DF - 1)];
    #pragma unroll
    for (int sl = 0; sl < KSPLIT1; sl++) s += part[sl * (BDIM * DF) + i];
    s = fmaxf(s, 0.f);
    Ah[i] = __float2half_rn(s);
}

// ---------------------------------------------------------------------------
// W_hyper [256, 98304] fp32 -> transposed fp16 [98304, 256]
// ---------------------------------------------------------------------------
__global__ void __launch_bounds__(256)
transpose_convert_k(const float* __restrict__ W, __half* __restrict__ Bh)
{
    __shared__ float s[64][65];
    const int n0 = blockIdx.x * 64, k0 = blockIdx.y * 64;
    const int t = threadIdx.x;
    {
        const int nn = t & 63, kk = t >> 6;
        #pragma unroll
        for (int p = 0; p < 16; p++) {
            int k = kk + p * 4;
            s[k][nn] = W[(size_t)(k0 + k) * NW + n0 + nn];
        }
    }
    __syncthreads();
    const int n = t >> 2, su = (t & 3) * 16;
    __align__(16) __half hi[16];
    #pragma unroll
    for (int i = 0; i < 16; i++)
        hi[i] = __float2half_rn(s[su + i][n]);
    const size_t o = (size_t)(n0 + n) * DF + k0 + su;
    *(int4*)(Bh + o)     = *(int4*)hi;
    *(int4*)(Bh + o + 8) = *(int4*)(hi + 8);
}

// ---------------------------------------------------------------------------
// fp16 mma GEMM: C[128m x 128n] = A[128,256] @ B[128rows,256]^T, single term.
// 3-stage cp.async pipeline (K-chunk 64), one sync per stage.
// V mode (pred==nullptr): C+bias -> vout.  U mode: contract with t -> pred.
// ---------------------------------------------------------------------------
__global__ void __launch_bounds__(256, 2)
gemm_mma_k(const __half* __restrict__ Ahg, const __half* __restrict__ Bhg,
           const float* __restrict__ bias, const float* __restrict__ tvec,
           float* __restrict__ vout, float* __restrict__ pred, int ntile0)
{
    extern __shared__ char smem[];
    const uint32_t sb = smem_u32(smem);
    const int tid = threadIdx.x, wid = tid >> 5, lane = tid & 31;
    const int bm = blockIdx.x;                 // fast dim -> B tile L2 reuse
    const int ntile = ntile0 + blockIdx.y;
    const int m0 = bm * 128, nrow0 = ntile * 128;
    const int warp_m = wid & 1, warp_n = wid >> 1;   // 2x4 warps: 64m x 32n each
    const int g = lane >> 2, t4 = lane & 3;

    float acc[4][4][4];
    #pragma unroll
    for (int mf = 0; mf < 4; mf++)
        #pragma unroll
        for (int nf = 0; nf < 4; nf++)
            #pragma unroll
            for (int c = 0; c < 4; c++) acc[mf][nf][c] = 0.f;

    const int a_row = warp_m * 64 + (lane & 15);
    const int a_koff = (lane >> 4) * 8;
    const int b_row = lane & 7;
    const int b_koff = ((lane >> 3) & 1) * 8;

    const __half* Asrc = Ahg + (size_t)m0 * DF;
    const __half* Bsrc = Bhg + (size_t)nrow0 * DF;

    auto load_stage = [&](int buf, int k0) {
        // each tile: 128 rows x 64 k fp16 = 8 int4/row = 1024 transfers
        #pragma unroll
        for (int p = 0; p < 4; p++) {
            const int c = tid + p * 256;
            const int row = c >> 3, j = c & 7;
            const uint32_t so = (uint32_t)(row * LDA + j * 8) * 2;
            const size_t go = (size_t)row * DF + k0 + j * 8;
            CP_ASYNC16(sb + OFF_A(buf) + so, Asrc + go);
            CP_ASYNC16(sb + OFF_B(buf) + so, Bsrc + go);
        }
    };

    auto compute = [&](int buf) {
        const uint32_t a_base = sb + OFF_A(buf);
        const uint32_t b_base = sb + OFF_B(buf);
        #pragma unroll
        for (int ks = 0; ks < 4; ks++) {
            uint32_t bh[4][2];
            #pragma unroll
            for (int nf = 0; nf < 4; nf++) {
                const uint32_t bo = (uint32_t)((warp_n * 32 + nf * 8 + b_row) * LDA
                                               + ks * 16 + b_koff) * 2;
                LDMX2(bh[nf][0], bh[nf][1], b_base + bo);
            }
            #pragma unroll
            for (int mf = 0; mf < 4; mf++) {
                uint32_t ah[4];
                const uint32_t so = (uint32_t)((a_row + mf * 16) * LDA + ks * 16 + a_koff) * 2;
                LDMX4(ah[0], ah[1], ah[2], ah[3], a_base + so);
                #pragma unroll
                for (int nf = 0; nf < 4; nf++)
                    mma_f16(acc[mf][nf], ah[0], ah[1], ah[2], ah[3], bh[nf][0], bh[nf][1]);
            }
        }
    };

    // --- 3-stage pipeline, one barrier per stage ---
    load_stage(0, 0);
    CP_COMMIT();
    load_stage(1, KCH);
    CP_COMMIT();
    #pragma unroll
    for (int s = 0; s < NSTG; s++) {
        if (s + 1 < NSTG) CP_WAIT1(); else CP_WAIT0();  // stage s landed
        __syncthreads();        // all threads see stage s; buf (s-1)%3 free
        if (s + 2 < NSTG) {
            load_stage((s + 2) % 3, (s + 2) * KCH);
            CP_COMMIT();
        }
        compute(s % 3);
    }
    __syncthreads();            // epilogue reuses smem (U mode)

    // ------------------------- epilogue -------------------------
    if (pred == nullptr) {
        // V mode: C + bias -> vout
        #pragma unroll
        for (int mf = 0; mf < 4; mf++) {
            const int row = warp_m * 64 + mf * 16 + g;
            #pragma unroll
            for (int nf = 0; nf < 4; nf++) {
                const int col = warp_n * 32 + nf * 8 + 2 * t4;
                const float b0 = bias[nrow0 + col], b1 = bias[nrow0 + col + 1];
                const size_t base = (size_t)(m0 + row) * HALF + (nrow0 - HALF) + col;
                float2 v0 = make_float2(acc[mf][nf][0] + b0, acc[mf][nf][1] + b1);
                float2 v1 = make_float2(acc[mf][nf][2] + b0, acc[mf][nf][3] + b1);
                *(float2*)&vout[base] = v0;
                *(float2*)&vout[base + (size_t)8 * HALF] = v1;
            }
        }
    } else {
        // U mode: pred[b, i] = sum_col (C+bias) * t[b, col&63]
        float* spart = (float*)smem;
        #pragma unroll
        for (int mf = 0; mf < 4; mf++) {
            const int row_lo = warp_m * 64 + mf * 16 + g;
            float p0 = 0.f, p1 = 0.f;
            const float* t0p = tvec + (size_t)(m0 + row_lo) * RANK;
            const float* t1p = tvec + (size_t)(m0 + row_lo + 8) * RANK;
            #pragma unroll
            for (int nf = 0; nf < 4; nf++) {
                const int col = warp_n * 32 + nf * 8 + 2 * t4;
                const int r = col & 63;
                const float b0 = bias[nrow0 + col], b1 = bias[nrow0 + col + 1];
                p0 += (acc[mf][nf][0] + b0) * t0p[r] + (acc[mf][nf][1] + b1) * t0p[r + 1];
                p1 += (acc[mf][nf][2] + b0) * t1p[r] + (acc[mf][nf][3] + b1) * t1p[r + 1];
            }
            p0 += __shfl_xor_sync(0xFFFFFFFF, p0, 1);
            p0 += __shfl_xor_sync(0xFFFFFFFF, p0, 2);
            p1 += __shfl_xor_sync(0xFFFFFFFF, p1, 1);
            p1 += __shfl_xor_sync(0xFFFFFFFF, p1, 2);
            if (t4 == 0) {
                spart[row_lo * 4 + warp_n] = p0;
                spart[(row_lo + 8) * 4 + warp_n] = p1;
            }
        }
        __syncthreads();
        {
            const int row = tid >> 1, ih = tid & 1;
            const float v = spart[row * 4 + 2 * ih] + spart[row * 4 + 2 * ih + 1];
            pred[(size_t)(m0 + row) * CELL + 2 * ntile + ih] = v;
        }
    }
}

// ---------------------------------------------------------------------------
// t[b,r] = sum_j V[b,j,r] * x[b,j]  (float4 vectorized)
// ---------------------------------------------------------------------------
__global__ void compute_t_k(const float* __restrict__ v, const float* __restrict__ x,
                            float* __restrict__ t)
{
    const int b = blockIdx.x;
    const int tid = threadIdx.x;
    __shared__ float sx[CELL];
    __shared__ float red[16][68];
    for (int j = tid; j < CELL; j += 256) sx[j] = x[(size_t)b * CELL + j];
    __syncthreads();
    const int rq = tid & 15;
    const int jg = tid >> 4;
    const float* vb = v + (size_t)b * HALF;
    float4 a = make_float4(0.f, 0.f, 0.f, 0.f);
    for (int j = jg; j < CELL; j += 16) {
        float4 w = *(const float4*)(vb + j * 64 + rq * 4);
        const float xx = sx[j];
        a.x += w.x * xx; a.y += w.y * xx; a.z += w.z * xx; a.w += w.w * xx;
    }
    *(float4*)&red[jg][rq * 4] = a;
    __syncthreads();
    if (tid < 64) {
        float s = 0.f;
        #pragma unroll
        for (int gg = 0; gg < 16; gg++) s += red[gg][tid];
        t[b * RANK + tid] = s;
    }
}

// ---------------------------------------------------------------------------
// launch
// ---------------------------------------------------------------------------
extern "C" void kernel_launch(void* const* d_in, const int* in_sizes, int n_in,
                              void* d_out, int out_size)
{
    const float* x     = (const float*)d_in[0];
    const float* seq   = (const float*)d_in[1];
    const float* W_dna = (const float*)d_in[2];
    const float* b_dna = (const float*)d_in[3];
    const float* W_hyp = (const float*)d_in[4];
    const float* b_hyp = (const float*)d_in[5];
    float* out = (float*)d_out;

    float *p_part, *p_v, *p_t;
    __half *p_Ah, *p_Bh;
    cudaGetSymbolAddress((void**)&p_part, g_part);
    cudaGetSymbolAddress((void**)&p_Ah, g_Ah);
    cudaGetSymbolAddress((void**)&p_Bh, g_Bh);
    cudaGetSymbolAddress((void**)&p_v, g_v);
    cudaGetSymbolAddress((void**)&p_t, g_t);

    cudaFuncSetAttribute(gemm_mma_k, cudaFuncAttributeMaxDynamicSharedMemorySize, GEMM2_SMEM);

    // W_hyper -> transposed fp16 [98304, 256]
    {
        dim3 grid(NW / 64, DF / 64);
        transpose_convert_k<<<grid, 256>>>(W_hyp, p_Bh);
    }
    // GEMM1 split-K + epilogue (bias, relu, fp16)
    {
        dim3 grid(DF / 128, BDIM / 128, KSPLIT1);
        sgemm_k<<<grid, 256>>>(seq, W_dna, p_part, BDIM, DF, KDNA);
    }
    reduce_relu_convert_k<<<(BDIM * DF) / 256, 256>>>(p_part, b_dna, p_Ah);

    // V-GEMM: 128-col n-tiles [384, 768) -> g_v (+bias)
    {
        dim3 grid(BDIM / 128, 384);
        gemm_mma_k<<<grid, 256, GEMM2_SMEM>>>(p_Ah, p_Bh, b_hyp,
                                              nullptr, p_v, nullptr, 384);
    }
    // t = V^T x
    compute_t_k<<<BDIM, 256>>>(p_v, x, p_t);

    // U-GEMM: 128-col n-tiles [0, 384) fused with t-contraction -> out
    {
        dim3 grid(BDIM / 128, 384);
        gemm_mma_k<<<grid, 256, GEMM2_SMEM>>>(p_Ah, p_Bh, b_hyp,
                                              p_t, nullptr, out, 0);
    }
}

// round 12
// speedup vs baseline: 1.8987x; 1.1046x over previous
#include <cuda_runtime.h>
#include <cuda_fp16.h>
#include <cstdint>
#include <cstddef>

#define BDIM   512
#define CELL   768
#define RANK   64
#define DF     256
#define KDNA   4000
#define NW     98304
#define HALF   49152
#define KSPLIT1 20

// GEMM2 tiling: CTA = 128m x 128n, K-chunk 64, 4 stages, 3-buffer pipeline
#define KCH    64
#define NSTG   4
#define LDA    72                        // smem stride (fp16): 144B rows, conflict-free ldmatrix
#define A_TILE (128 * LDA * 2)           // 18432 bytes (one of Ah/B)
#define OFF_A(buf) ((buf) * A_TILE)
#define OFF_B(buf) (3 * A_TILE + (buf) * A_TILE)
#define GEMM2_SMEM (6 * A_TILE)          // 110592

// ---------------------------------------------------------------------------
// asm helpers (proven R5/R8-R11)
// ---------------------------------------------------------------------------
__device__ __forceinline__ void mma_f16(float c[4],
                                        uint32_t a0, uint32_t a1, uint32_t a2, uint32_t a3,
                                        uint32_t b0, uint32_t b1)
{
    asm volatile(
        "mma.sync.aligned.m16n8k16.row.col.f32.f16.f16.f32 "
        "{%0,%1,%2,%3}, {%4,%5,%6,%7}, {%8,%9}, {%0,%1,%2,%3};"
        : "+f"(c[0]), "+f"(c[1]), "+f"(c[2]), "+f"(c[3])
        : "r"(a0), "r"(a1), "r"(a2), "r"(a3), "r"(b0), "r"(b1));
}
__device__ __forceinline__ uint32_t smem_u32(const void* p) {
    uint32_t a;
    asm("{ .reg .u64 t; cvta.to.shared.u64 t, %1; cvt.u32.u64 %0, t; }" : "=r"(a) : "l"(p));
    return a;
}
#define LDMX4(r0, r1, r2, r3, addr) \
    asm volatile("ldmatrix.sync.aligned.m8n8.x4.shared.b16 {%0,%1,%2,%3}, [%4];" \
                 : "=r"(r0), "=r"(r1), "=r"(r2), "=r"(r3) : "r"(addr))
#define CP_ASYNC16(dst, src) \
    asm volatile("cp.async.cg.shared.global [%0], [%1], 16;" :: "r"(dst), "l"(src))
#define CP_COMMIT() asm volatile("cp.async.commit_group;" ::: "memory")
#define CP_WAIT1()  asm volatile("cp.async.wait_group 1;" ::: "memory")
#define CP_WAIT0()  asm volatile("cp.async.wait_group 0;" ::: "memory")

// ---------------------------------------------------------------------------
// device scratch
// ---------------------------------------------------------------------------
__device__ float g_part[KSPLIT1 * BDIM * DF];
__device__ __align__(256) __half g_Ah[BDIM * DF];
__device__ __align__(256) __half g_Bh[(size_t)NW * DF];   // W_hyper^T fp16 [n][k]
__device__ __align__(256) __half g_v[(size_t)BDIM * HALF]; // V half (+bias), fp16
__device__ float g_t[BDIM * RANK];

// ---------------------------------------------------------------------------
// GEMM1: SIMT 128x128x8 SGEMM, split-K partials
// ---------------------------------------------------------------------------
__global__ void __launch_bounds__(256, 2)
sgemm_k(const float* __restrict__ A, const float* __restrict__ Bmat,
        float* __restrict__ C, int M, int N, int K)
{
    const int bn = blockIdx.x, bm = blockIdx.y, slice = blockIdx.z;
    const int kPer = K / gridDim.z;
    const int k0base = slice * kPer;

    __shared__ float As[8][128];
    __shared__ float Bs[8][128];

    const int tid = threadIdx.x;
    const int aRow = tid >> 1, aK4 = (tid & 1) * 4;
    const int bK = tid >> 5, bN4 = (tid & 31) * 4;
    const int tx = tid & 15, ty = tid >> 4;

    float acc[8][8];
    #pragma unroll
    for (int i = 0; i < 8; i++)
        #pragma unroll
        for (int j = 0; j < 8; j++) acc[i][j] = 0.f;

    const float* Aptr = A + (size_t)(bm * 128 + aRow) * K + k0base + aK4;
    const float* Bptr = Bmat + (size_t)(k0base + bK) * N + (size_t)bn * 128 + bN4;

    const int nsteps = kPer / 8;
    for (int kt = 0; kt < nsteps; kt++) {
        float4 av = *(const float4*)(Aptr);
        float4 bv = *(const float4*)(Bptr);
        As[aK4 + 0][aRow] = av.x; As[aK4 + 1][aRow] = av.y;
        As[aK4 + 2][aRow] = av.z; As[aK4 + 3][aRow] = av.w;
        *(float4*)&Bs[bK][bN4] = bv;
        __syncthreads();
        #pragma unroll
        for (int k = 0; k < 8; k++) {
            float af[8], bf[8];
            #pragma unroll
            for (int i = 0; i < 8; i++) af[i] = As[k][ty * 8 + i];
            #pragma unroll
            for (int j = 0; j < 8; j++) bf[j] = Bs[k][tx * 8 + j];
            #pragma unroll
            for (int i = 0; i < 8; i++)
                #pragma unroll
                for (int j = 0; j < 8; j++) acc[i][j] += af[i] * bf[j];
        }
        __syncthreads();
        Aptr += 8;
        Bptr += (size_t)8 * N;
    }
    float* Cbase = C + (size_t)slice * M * N;
    #pragma unroll
    for (int i = 0; i < 8; i++) {
        const int row = bm * 128 + ty * 8 + i;
        #pragma unroll
        for (int j = 0; j < 8; j += 4) {
            const int col = bn * 128 + tx * 8 + j;
            float4 v = make_float4(acc[i][j], acc[i][j+1], acc[i][j+2], acc[i][j+3]);
            *(float4*)(Cbase + (size_t)row * N + col) = v;
        }
    }
}

// ---------------------------------------------------------------------------
// reduce split-K + bias + relu -> fp16 A
// ---------------------------------------------------------------------------
__global__ void reduce_relu_convert_k(const float* __restrict__ part,
                                      const float* __restrict__ bias,
                                      __half* __restrict__ Ah)
{
    const int i = blockIdx.x * 256 + threadIdx.x;
    float s = bias[i & (DF - 1)];
    #pragma unroll
    for (int sl = 0; sl < KSPLIT1; sl++) s += part[sl * (BDIM * DF) + i];
    s = fmaxf(s, 0.f);
    Ah[i] = __float2half_rn(s);
}

// ---------------------------------------------------------------------------
// W_hyper [256, 98304] fp32 -> transposed fp16 [98304, 256]
// ---------------------------------------------------------------------------
__global__ void __launch_bounds__(256)
transpose_convert_k(const float* __restrict__ W, __half* __restrict__ Bh)
{
    __shared__ float s[64][65];
    const int n0 = blockIdx.x * 64, k0 = blockIdx.y * 64;
    const int t = threadIdx.x;
    {
        const int nn = t & 63, kk = t >> 6;
        #pragma unroll
        for (int p = 0; p < 16; p++) {
            int k = kk + p * 4;
            s[k][nn] = W[(size_t)(k0 + k) * NW + n0 + nn];
        }
    }
    __syncthreads();
    const int n = t >> 2, su = (t & 3) * 16;
    __align__(16) __half hi[16];
    #pragma unroll
    for (int i = 0; i < 16; i++)
        hi[i] = __float2half_rn(s[su + i][n]);
    const size_t o = (size_t)(n0 + n) * DF + k0 + su;
    *(int4*)(Bh + o)     = *(int4*)hi;
    *(int4*)(Bh + o + 8) = *(int4*)(hi + 8);
}

// ---------------------------------------------------------------------------
// fp16 mma GEMM: C[128m x 128n] = A[128,256] @ B[128rows,256]^T, single term.
// 3-stage cp.async pipeline (K-chunk 64), one sync per stage.
// V mode (pred==nullptr): C+bias -> vout (fp16).  U mode: contract with t -> pred.
// ---------------------------------------------------------------------------
__global__ void __launch_bounds__(256, 2)
gemm_mma_k(const __half* __restrict__ Ahg, const __half* __restrict__ Bhg,
           const float* __restrict__ bias, const float* __restrict__ tvec,
           __half* __restrict__ vout, float* __restrict__ pred, int ntile0)
{
    extern __shared__ char smem[];
    const uint32_t sb = smem_u32(smem);
    const int tid = threadIdx.x, wid = tid >> 5, lane = tid & 31;
    const int bm = blockIdx.x;                 // fast dim -> B tile L2 reuse
    const int ntile = ntile0 + blockIdx.y;
    const int m0 = bm * 128, nrow0 = ntile * 128;
    const int warp_m = wid & 1, warp_n = wid >> 1;   // 2x4 warps: 64m x 32n each
    const int g = lane >> 2, t4 = lane & 3;

    float acc[4][4][4];
    #pragma unroll
    for (int mf = 0; mf < 4; mf++)
        #pragma unroll
        for (int nf = 0; nf < 4; nf++)
            #pragma unroll
            for (int c = 0; c < 4; c++) acc[mf][nf][c] = 0.f;

    const int a_row = warp_m * 64 + (lane & 15);
    const int a_koff = (lane >> 4) * 8;
    // B x4 lane mapping: matrices 0..3 = (nf_lo,k_lo),(nf_lo,k_hi),(nf_hi,k_lo),(nf_hi,k_hi)
    const int b_row4 = warp_n * 32 + ((lane >> 4) & 1) * 8 + (lane & 7);
    const int b_koff = ((lane >> 3) & 1) * 8;

    const __half* Asrc = Ahg + (size_t)m0 * DF;
    const __half* Bsrc = Bhg + (size_t)nrow0 * DF;

    auto load_stage = [&](int buf, int k0) {
        // each tile: 128 rows x 64 k fp16 = 8 int4/row = 1024 transfers
        #pragma unroll
        for (int p = 0; p < 4; p++) {
            const int c = tid + p * 256;
            const int row = c >> 3, j = c & 7;
            const uint32_t so = (uint32_t)(row * LDA + j * 8) * 2;
            const size_t go = (size_t)row * DF + k0 + j * 8;
            CP_ASYNC16(sb + OFF_A(buf) + so, Asrc + go);
            CP_ASYNC16(sb + OFF_B(buf) + so, Bsrc + go);
        }
    };

    auto compute = [&](int buf) {
        const uint32_t a_base = sb + OFF_A(buf);
        const uint32_t b_base = sb + OFF_B(buf);
        #pragma unroll
        for (int ks = 0; ks < 4; ks++) {
            uint32_t bh[4][2];
            #pragma unroll
            for (int p = 0; p < 2; p++) {
                const uint32_t bo = (uint32_t)((b_row4 + p * 16) * LDA
                                               + ks * 16 + b_koff) * 2;
                LDMX4(bh[2*p][0], bh[2*p][1], bh[2*p+1][0], bh[2*p+1][1], b_base + bo);
            }
            #pragma unroll
            for (int mf = 0; mf < 4; mf++) {
                uint32_t ah[4];
                const uint32_t so = (uint32_t)((a_row + mf * 16) * LDA + ks * 16 + a_koff) * 2;
                LDMX4(ah[0], ah[1], ah[2], ah[3], a_base + so);
                #pragma unroll
                for (int nf = 0; nf < 4; nf++)
                    mma_f16(acc[mf][nf], ah[0], ah[1], ah[2], ah[3], bh[nf][0], bh[nf][1]);
            }
        }
    };

    // --- 3-stage pipeline, one barrier per stage ---
    load_stage(0, 0);
    CP_COMMIT();
    load_stage(1, KCH);
    CP_COMMIT();
    #pragma unroll
    for (int s = 0; s < NSTG; s++) {
        if (s + 1 < NSTG) CP_WAIT1(); else CP_WAIT0();  // stage s landed
        __syncthreads();        // all threads see stage s; buf (s-1)%3 free
        if (s + 2 < NSTG) {
            load_stage((s + 2) % 3, (s + 2) * KCH);
            CP_COMMIT();
        }
        compute(s % 3);
    }
    __syncthreads();            // epilogue reuses smem (U mode)

    // ------------------------- epilogue -------------------------
    if (pred == nullptr) {
        // V mode: C + bias -> vout (fp16 half2 stores)
        #pragma unroll
        for (int mf = 0; mf < 4; mf++) {
            const int row = warp_m * 64 + mf * 16 + g;
            #pragma unroll
            for (int nf = 0; nf < 4; nf++) {
                const int col = warp_n * 32 + nf * 8 + 2 * t4;
                const float b0 = bias[nrow0 + col], b1 = bias[nrow0 + col + 1];
                const size_t base = (size_t)(m0 + row) * HALF + (nrow0 - HALF) + col;
                __half2 v0 = __floats2half2_rn(acc[mf][nf][0] + b0, acc[mf][nf][1] + b1);
                __half2 v1 = __floats2half2_rn(acc[mf][nf][2] + b0, acc[mf][nf][3] + b1);
                *(__half2*)&vout[base] = v0;
                *(__half2*)&vout[base + (size_t)8 * HALF] = v1;
            }
        }
    } else {
        // U mode: pred[b, i] = sum_col (C+bias) * t[b, col&63]
        float* spart = (float*)smem;
        #pragma unroll
        for (int mf = 0; mf < 4; mf++) {
            const int row_lo = warp_m * 64 + mf * 16 + g;
            float p0 = 0.f, p1 = 0.f;
            const float* t0p = tvec + (size_t)(m0 + row_lo) * RANK;
            const float* t1p = tvec + (size_t)(m0 + row_lo + 8) * RANK;
            #pragma unroll
            for (int nf = 0; nf < 4; nf++) {
                const int col = warp_n * 32 + nf * 8 + 2 * t4;
                const int r = col & 63;
                const float b0 = bias[nrow0 + col], b1 = bias[nrow0 + col + 1];
                p0 += (acc[mf][nf][0] + b0) * t0p[r] + (acc[mf][nf][1] + b1) * t0p[r + 1];
                p1 += (acc[mf][nf][2] + b0) * t1p[r] + (acc[mf][nf][3] + b1) * t1p[r + 1];
            }
            p0 += __shfl_xor_sync(0xFFFFFFFF, p0, 1);
            p0 += __shfl_xor_sync(0xFFFFFFFF, p0, 2);
            p1 += __shfl_xor_sync(0xFFFFFFFF, p1, 1);
            p1 += __shfl_xor_sync(0xFFFFFFFF, p1, 2);
            if (t4 == 0) {
                spart[row_lo * 4 + warp_n] = p0;
                spart[(row_lo + 8) * 4 + warp_n] = p1;
            }
        }
        __syncthreads();
        {
            const int row = tid >> 1, ih = tid & 1;
            const float v = spart[row * 4 + 2 * ih] + spart[row * 4 + 2 * ih + 1];
            pred[(size_t)(m0 + row) * CELL + 2 * ntile + ih] = v;
        }
    }
}

// ---------------------------------------------------------------------------
// t[b,r] = sum_j V[b,j,r] * x[b,j]  (fp16 V, int4 = 8 halves per load)
// ---------------------------------------------------------------------------
__global__ void compute_t_k(const __half* __restrict__ v, const float* __restrict__ x,
                            float* __restrict__ t)
{
    const int b = blockIdx.x;
    const int tid = threadIdx.x;
    __shared__ float sx[CELL];
    __shared__ float red[32][72];
    for (int j = tid; j < CELL; j += 256) sx[j] = x[(size_t)b * CELL + j];
    __syncthreads();
    const int rq = tid & 7;             // r-octet: r = rq*8 .. +7
    const int jg = tid >> 3;            // 32 j groups
    const __half* vb = v + (size_t)b * HALF;
    float a[8];
    #pragma unroll
    for (int q = 0; q < 8; q++) a[q] = 0.f;
    for (int j = jg; j < CELL; j += 32) {
        int4 w = *(const int4*)(vb + j * 64 + rq * 8);
        const __half2* h = (const __half2*)&w;
        const float xx = sx[j];
        #pragma unroll
        for (int q = 0; q < 4; q++) {
            float2 f = __half22float2(h[q]);
            a[2 * q]     += f.x * xx;
            a[2 * q + 1] += f.y * xx;
        }
    }
    #pragma unroll
    for (int q = 0; q < 8; q++) red[jg][rq * 8 + q] = a[q];
    __syncthreads();
    if (tid < 64) {
        float s = 0.f;
        #pragma unroll
        for (int gg = 0; gg < 32; gg++) s += red[gg][tid];
        t[b * RANK + tid] = s;
    }
}

// ---------------------------------------------------------------------------
// launch
// ---------------------------------------------------------------------------
extern "C" void kernel_launch(void* const* d_in, const int* in_sizes, int n_in,
                              void* d_out, int out_size)
{
    const float* x     = (const float*)d_in[0];
    const float* seq   = (const float*)d_in[1];
    const float* W_dna = (const float*)d_in[2];
    const float* b_dna = (const float*)d_in[3];
    const float* W_hyp = (const float*)d_in[4];
    const float* b_hyp = (const float*)d_in[5];
    float* out = (float*)d_out;

    float *p_part, *p_t;
    __half *p_Ah, *p_Bh, *p_v;
    cudaGetSymbolAddress((void**)&p_part, g_part);
    cudaGetSymbolAddress((void**)&p_Ah, g_Ah);
    cudaGetSymbolAddress((void**)&p_Bh, g_Bh);
    cudaGetSymbolAddress((void**)&p_v, g_v);
    cudaGetSymbolAddress((void**)&p_t, g_t);

    cudaFuncSetAttribute(gemm_mma_k, cudaFuncAttributeMaxDynamicSharedMemorySize, GEMM2_SMEM);

    // W_hyper -> transposed fp16 [98304, 256]
    {
        dim3 grid(NW / 64, DF / 64);
        transpose_convert_k<<<grid, 256>>>(W_hyp, p_Bh);
    }
    // GEMM1 split-K + epilogue (bias, relu, fp16)
    {
        dim3 grid(DF / 128, BDIM / 128, KSPLIT1);
        sgemm_k<<<grid, 256>>>(seq, W_dna, p_part, BDIM, DF, KDNA);
    }
    reduce_relu_convert_k<<<(BDIM * DF) / 256, 256>>>(p_part, b_dna, p_Ah);

    // V-GEMM: 128-col n-tiles [384, 768) -> g_v (+bias, fp16)
    {
        dim3 grid(BDIM / 128, 384);
        gemm_mma_k<<<grid, 256, GEMM2_SMEM>>>(p_Ah, p_Bh, b_hyp,
                                              nullptr, p_v, nullptr, 384);
    }
    // t = V^T x
    compute_t_k<<<BDIM, 256>>>(p_v, x, p_t);

    // U-GEMM: 128-col n-tiles [0, 384) fused with t-contraction -> out
    {
        dim3 grid(BDIM / 128, 384);
        gemm_mma_k<<<grid, 256, GEMM2_SMEM>>>(p_Ah, p_Bh, b_hyp,
                                              p_t, nullptr, out, 0);
    }
}